// round 8
// baseline (speedup 1.0000x reference)
#include <cuda_runtime.h>
#include <cuda_bf16.h>
#include <cstdint>

// ================================================================
// AutoGNN, 7 launches:
//   1) split_w:  W1/W2/WL -> bf16 hi/lo (WL padded 40->64 rows)
//   2) split_x:  X -> (Xhi,Xlo)
//   3) gemm:     Y = (Xhi+Xlo) @ W1^T     [persistent, cp.async pipelined]
//   4) gather:   (Ahi,Alo) = split(relu(mean(Y[nbrs])))
//   5) gemm:     Y = (Ahi+Alo) @ W2^T
//   6) gather
//   7) gemm<64,40>: out = (Ahi+Alo) @ WL^T
// GEMM inner loop: k-outer / split-inner — load 8 fragments per
// k-step (A-hi, A-lo, B-hi, B-lo), issue 24 mma against them
// (hi*hi + hi*lo + lo*hi). 64 ldsm / 192 mma per warp-tile.
// ================================================================

#define FEAT 128
#define SAMPLE 25
#define CLASSES 40
#define MAXN 100000
#define RS 272   // smem row stride bytes (136 bf16): conflict-free ldmatrix
#define NGEMM_CTAS 152

__device__ float         g_Y  [(size_t)MAXN * FEAT];
__device__ __nv_bfloat16 g_Ahi[(size_t)MAXN * FEAT];
__device__ __nv_bfloat16 g_Alo[(size_t)MAXN * FEAT];
__device__ __nv_bfloat16 g_Xhi[(size_t)MAXN * FEAT];
__device__ __nv_bfloat16 g_Xlo[(size_t)MAXN * FEAT];
__device__ __nv_bfloat16 g_W1hi[128 * 128], g_W1lo[128 * 128];
__device__ __nv_bfloat16 g_W2hi[128 * 128], g_W2lo[128 * 128];
__device__ __nv_bfloat16 g_WLhi[64 * 128],  g_WLlo[64 * 128];

__device__ __forceinline__ uint32_t smem_u32(const void* p) {
    uint32_t a;
    asm("{ .reg .u64 t; cvta.to.shared.u64 t, %1; cvt.u32.u64 %0, t; }" : "=r"(a) : "l"(p));
    return a;
}
__device__ __forceinline__ void ldsm4(uint32_t addr, uint32_t& r0, uint32_t& r1,
                                      uint32_t& r2, uint32_t& r3) {
    asm volatile("ldmatrix.sync.aligned.m8n8.x4.shared.b16 {%0,%1,%2,%3}, [%4];"
                 : "=r"(r0), "=r"(r1), "=r"(r2), "=r"(r3) : "r"(addr));
}
__device__ __forceinline__ void mma_bf16(float* c, const uint32_t* a,
                                         uint32_t b0, uint32_t b1) {
    asm volatile(
        "mma.sync.aligned.m16n8k16.row.col.f32.bf16.bf16.f32 "
        "{%0,%1,%2,%3}, {%4,%5,%6,%7}, {%8,%9}, {%0,%1,%2,%3};"
        : "+f"(c[0]), "+f"(c[1]), "+f"(c[2]), "+f"(c[3])
        : "r"(a[0]), "r"(a[1]), "r"(a[2]), "r"(a[3]), "r"(b0), "r"(b1));
}
__device__ __forceinline__ void cp_async16(uint32_t saddr, const void* gaddr,
                                           uint32_t src_sz) {
    asm volatile("cp.async.cg.shared.global [%0], [%1], 16, %2;"
                 :: "r"(saddr), "l"(gaddr), "r"(src_sz));
}
#define CP_COMMIT() asm volatile("cp.async.commit_group;" ::: "memory")
#define CP_WAIT1()  asm volatile("cp.async.wait_group 1;" ::: "memory")

// ================================================================
// Persistent pipelined GEMM: C[t*128.., CST] = (Ahi+Alo) @ (Whi+Wlo)^T
// smem: [Whi NOUT*RS][Wlo NOUT*RS][buf0: Ahi 128*RS, Alo 128*RS][buf1: ...]
// ================================================================
template<int NOUT, int CST>
__global__ __launch_bounds__(512, 1) void gemm_pipe_kernel(
    const __nv_bfloat16* __restrict__ Ahi, const __nv_bfloat16* __restrict__ Alo,
    const __nv_bfloat16* __restrict__ Whi, const __nv_bfloat16* __restrict__ Wlo,
    float* __restrict__ C, int n)
{
    extern __shared__ char smem[];
    constexpr int OFF_WLO = NOUT * RS;
    constexpr int OFF_A0  = 2 * NOUT * RS;
    constexpr int ABUF    = 2 * 128 * RS;      // hi+lo per buffer
    constexpr int WN = NOUT / 4;               // warp n-extent (32 or 16)
    constexpr int NT = WN / 8;                 // n8 tiles per warp (4 or 2)

    const int tid  = threadIdx.x;
    const int wid  = tid >> 5;
    const int lane = tid & 31;
    const int wm   = wid >> 2;                 // 0..3 -> m = wm*32
    const int wn   = wid & 3;                  // 0..3 -> n = wn*WN
    const uint32_t sb = smem_u32(smem);

    // ---- W resident load (once) ----
    #pragma unroll
    for (int i = 0; i < NOUT / 32; i++) {
        int t = i * 512 + tid;
        int row = t >> 4;
        int c16 = t & 15;
        size_t g = (size_t)row * 128 + c16 * 8;
        int off = row * RS + c16 * 16;
        *reinterpret_cast<uint4*>(smem + off) =
            *reinterpret_cast<const uint4*>(Whi + g);
        *reinterpret_cast<uint4*>(smem + OFF_WLO + off) =
            *reinterpret_cast<const uint4*>(Wlo + g);
    }

    const int tiles  = (n + 127) >> 7;
    const int stride = gridDim.x;

    // ---- A tile prefetch (cp.async, zfill OOB rows) ----
    auto prefetch = [&](int t, int buf) {
        const uint32_t abase = sb + OFF_A0 + buf * ABUF;
        const int m0 = t << 7;
        #pragma unroll
        for (int i = 0; i < 4; i++) {
            int k = i * 512 + tid;             // 2048: row 0..127, c16 0..15
            int row = k >> 4;
            int c16 = k & 15;
            int grow = m0 + row;
            uint32_t sz = (grow < n) ? 16u : 0u;
            int gc = (grow < n) ? grow : 0;
            size_t g = (size_t)gc * 128 + c16 * 8;
            uint32_t off = (uint32_t)(row * RS + c16 * 16);
            cp_async16(abase + off,             Ahi + g, sz);
            cp_async16(abase + 128 * RS + off,  Alo + g, sz);
        }
    };

    // lane-derived ldmatrix offsets
    const int l15   = lane & 15;
    const int aHalf = (lane & 16) ? 16 : 0;
    const uint32_t aRowOff0 = (uint32_t)((wm * 32 + l15) * RS + aHalf);
    const uint32_t aRowOff1 = aRowOff0 + 16 * RS;
    const int bRow  = (lane & 7) + ((lane & 16) ? 8 : 0);
    const int bHalf = (lane & 8) ? 16 : 0;
    uint32_t bRowByte[NT / 2];
    #pragma unroll
    for (int jp = 0; jp < NT / 2; jp++)
        bRowByte[jp] = (uint32_t)((wn * WN + jp * 16 + bRow) * RS + bHalf);

    int t0 = blockIdx.x;
    if (t0 < tiles) prefetch(t0, 0);
    CP_COMMIT();

    int it = 0;
    for (int t = t0; t < tiles; t += stride, it++) {
        const int buf = it & 1;
        int tn = t + stride;
        if (tn < tiles) prefetch(tn, buf ^ 1);
        CP_COMMIT();
        CP_WAIT1();
        __syncthreads();

        const uint32_t aHiB = sb + OFF_A0 + buf * ABUF;
        const uint32_t aLoB = aHiB + 128 * RS;
        const uint32_t wHiB = sb;
        const uint32_t wLoB = sb + OFF_WLO;

        float c[2][NT][4];
        #pragma unroll
        for (int mt = 0; mt < 2; mt++)
            #pragma unroll
            for (int j = 0; j < NT; j++)
                #pragma unroll
                for (int q = 0; q < 4; q++) c[mt][j][q] = 0.f;

        // ---- k-outer / split-inner: 8 ldsm + 24 mma per k-step ----
        #pragma unroll
        for (int ks = 0; ks < 8; ks++) {
            const uint32_t kb = ks * 32;
            uint32_t ah[2][4], al[2][4];
            ldsm4(aHiB + aRowOff0 + kb, ah[0][0], ah[0][1], ah[0][2], ah[0][3]);
            ldsm4(aHiB + aRowOff1 + kb, ah[1][0], ah[1][1], ah[1][2], ah[1][3]);
            ldsm4(aLoB + aRowOff0 + kb, al[0][0], al[0][1], al[0][2], al[0][3]);
            ldsm4(aLoB + aRowOff1 + kb, al[1][0], al[1][1], al[1][2], al[1][3]);
            uint32_t bh[NT][2], bl[NT][2];
            #pragma unroll
            for (int jp = 0; jp < NT / 2; jp++) {
                ldsm4(wHiB + bRowByte[jp] + kb,
                      bh[2 * jp][0], bh[2 * jp][1], bh[2 * jp + 1][0], bh[2 * jp + 1][1]);
                ldsm4(wLoB + bRowByte[jp] + kb,
                      bl[2 * jp][0], bl[2 * jp][1], bl[2 * jp + 1][0], bl[2 * jp + 1][1]);
            }
            #pragma unroll
            for (int mt = 0; mt < 2; mt++)
                #pragma unroll
                for (int j = 0; j < NT; j++) {
                    mma_bf16(c[mt][j], ah[mt], bh[j][0], bh[j][1]);   // hi*hi
                    mma_bf16(c[mt][j], ah[mt], bl[j][0], bl[j][1]);   // hi*lo
                    mma_bf16(c[mt][j], al[mt], bh[j][0], bh[j][1]);   // lo*hi
                }
        }

        // ---- epilogue ----
        const int m0 = t << 7;
        const int qrow = lane >> 2;
        const int qcol = (lane & 3) * 2;
        #pragma unroll
        for (int mt = 0; mt < 2; mt++) {
            #pragma unroll
            for (int half = 0; half < 2; half++) {
                int m_g = m0 + wm * 32 + mt * 16 + qrow + half * 8;
                if (m_g < n) {
                    float* crow = C + (size_t)m_g * CST;
                    #pragma unroll
                    for (int j = 0; j < NT; j++) {
                        int n_g = wn * WN + j * 8 + qcol;
                        if (CST == 128 || n_g < CST) {
                            float2 v = make_float2(c[mt][j][half * 2],
                                                   c[mt][j][half * 2 + 1]);
                            *reinterpret_cast<float2*>(crow + n_g) = v;
                        }
                    }
                }
            }
        }
        __syncthreads();   // buf fully consumed before next iter refills it
    }
}

// ---------------- gather + split (high occupancy) ---------------------------
__global__ __launch_bounds__(256) void gather_split_kernel(
    const float* __restrict__ Y, const int* __restrict__ nbrs,
    __nv_bfloat16* __restrict__ Hhi, __nv_bfloat16* __restrict__ Hlo, int n)
{
    const int warp = (blockIdx.x * blockDim.x + threadIdx.x) >> 5;
    const int lane = threadIdx.x & 31;
    if (warp >= n) return;

    int idx = 0;
    if (lane < SAMPLE) idx = nbrs[(size_t)warp * SAMPLE + lane];

    float4 acc = make_float4(0.f, 0.f, 0.f, 0.f);
    #pragma unroll
    for (int j = 0; j < SAMPLE; j++) {
        int row = __shfl_sync(0xffffffffu, idx, j);
        float4 v = __ldg(reinterpret_cast<const float4*>(Y + (size_t)row * 128) + lane);
        acc.x += v.x; acc.y += v.y; acc.z += v.z; acc.w += v.w;
    }
    const float s = 1.0f / (float)SAMPLE;
    float o[4] = { fmaxf(acc.x * s, 0.f), fmaxf(acc.y * s, 0.f),
                   fmaxf(acc.z * s, 0.f), fmaxf(acc.w * s, 0.f) };
    __nv_bfloat16 h[4], l[4];
    #pragma unroll
    for (int q = 0; q < 4; q++) {
        h[q] = __float2bfloat16(o[q]);
        l[q] = __float2bfloat16(o[q] - __bfloat162float(h[q]));
    }
    *(reinterpret_cast<uint2*>(Hhi + (size_t)warp * 128) + lane) =
        *reinterpret_cast<uint2*>(h);
    *(reinterpret_cast<uint2*>(Hlo + (size_t)warp * 128) + lane) =
        *reinterpret_cast<uint2*>(l);
}

// ---------------- splitters --------------------------------------------------
__global__ void split_x_kernel(const float* __restrict__ X,
                               __nv_bfloat16* __restrict__ hi,
                               __nv_bfloat16* __restrict__ lo, int total4)
{
    int i = blockIdx.x * blockDim.x + threadIdx.x;
    if (i >= total4) return;
    float4 v = __ldg(reinterpret_cast<const float4*>(X) + i);
    float f[4] = { v.x, v.y, v.z, v.w };
    __nv_bfloat16 h[4], l[4];
    #pragma unroll
    for (int q = 0; q < 4; q++) {
        h[q] = __float2bfloat16(f[q]);
        l[q] = __float2bfloat16(f[q] - __bfloat162float(h[q]));
    }
    *(reinterpret_cast<uint2*>(hi) + i) = *reinterpret_cast<uint2*>(h);
    *(reinterpret_cast<uint2*>(lo) + i) = *reinterpret_cast<uint2*>(l);
}

__global__ void split_w_kernel(const float* __restrict__ W1,
                               const float* __restrict__ W2,
                               const float* __restrict__ WL,
                               __nv_bfloat16* w1h, __nv_bfloat16* w1l,
                               __nv_bfloat16* w2h, __nv_bfloat16* w2l,
                               __nv_bfloat16* wlh, __nv_bfloat16* wll)
{
    int i = blockIdx.x * blockDim.x + threadIdx.x;  // 0 .. 40959
    float v; __nv_bfloat16 *ph, *pl; int idx;
    if (i < 16384)      { v = W1[i];            ph = w1h; pl = w1l; idx = i; }
    else if (i < 32768) { idx = i - 16384; v = W2[idx]; ph = w2h; pl = w2l; }
    else if (i < 40960) {
        idx = i - 32768;                 // padded [64][128]
        int row = idx >> 7;
        v = (row < CLASSES) ? WL[idx] : 0.f;
        ph = wlh; pl = wll;
    } else return;
    __nv_bfloat16 h = __float2bfloat16(v);
    ph[idx] = h;
    pl[idx] = __float2bfloat16(v - __bfloat162float(h));
}

// ================================================================
extern "C" void kernel_launch(void* const* d_in, const int* in_sizes, int n_in,
                              void* d_out, int out_size)
{
    const float* X    = (const float*)d_in[0];
    const int*   nbrs = (const int*)  d_in[1];
    const float* W1   = (const float*)d_in[2];
    const float* W2   = (const float*)d_in[3];
    const float* WL   = (const float*)d_in[4];
    float*       out  = (float*)d_out;
    const int n = in_sizes[1] / SAMPLE;

    float* Y;
    __nv_bfloat16 *Ahi, *Alo, *Xhi, *Xlo, *w1h, *w1l, *w2h, *w2l, *wlh, *wll;
    cudaGetSymbolAddress((void**)&Y,   g_Y);
    cudaGetSymbolAddress((void**)&Ahi, g_Ahi);
    cudaGetSymbolAddress((void**)&Alo, g_Alo);
    cudaGetSymbolAddress((void**)&Xhi, g_Xhi);
    cudaGetSymbolAddress((void**)&Xlo, g_Xlo);
    cudaGetSymbolAddress((void**)&w1h, g_W1hi);
    cudaGetSymbolAddress((void**)&w1l, g_W1lo);
    cudaGetSymbolAddress((void**)&w2h, g_W2hi);
    cudaGetSymbolAddress((void**)&w2l, g_W2lo);
    cudaGetSymbolAddress((void**)&wlh, g_WLhi);
    cudaGetSymbolAddress((void**)&wll, g_WLlo);

    // smem: W (2*NOUT*RS) + 2 A buffers (2*128*RS each)
    const int SM128 = RS * (2 * 128) + 2 * RS * (2 * 128);  // 208896
    const int SM64  = RS * (2 * 64)  + 2 * RS * (2 * 128);  // 174080
    cudaFuncSetAttribute(gemm_pipe_kernel<128, 128>,
                         cudaFuncAttributeMaxDynamicSharedMemorySize, SM128);
    cudaFuncSetAttribute(gemm_pipe_kernel<64, 40>,
                         cudaFuncAttributeMaxDynamicSharedMemorySize, SM64);

    const int sg = (n * 32 + 255) / 256;
    const int ag = (n + 7) / 8;

    split_w_kernel<<<160, 256>>>(W1, W2, WL, w1h, w1l, w2h, w2l, wlh, wll);
    split_x_kernel<<<sg, 256>>>(X, Xhi, Xlo, n * 32);
    gemm_pipe_kernel<128, 128><<<NGEMM_CTAS, 512, SM128>>>(Xhi, Xlo, w1h, w1l, Y, n);
    gather_split_kernel<<<ag, 256>>>(Y, nbrs, Ahi, Alo, n);
    gemm_pipe_kernel<128, 128><<<NGEMM_CTAS, 512, SM128>>>(Ahi, Alo, w2h, w2l, Y, n);
    gather_split_kernel<<<ag, 256>>>(Y, nbrs, Ahi, Alo, n);
    gemm_pipe_kernel<64, 40><<<NGEMM_CTAS, 512, SM64>>>(Ahi, Alo, wlh, wll, out, n);
}

// round 9
// speedup vs baseline: 1.5441x; 1.5441x over previous
#include <cuda_runtime.h>
#include <cuda_fp16.h>
#include <cstdint>

// ================================================================
// AutoGNN, 6 launches — fp16 2-term split GEMMs:
//   Y = A @ (Wh + Wl)^T,  A = fp16(x) (single plane),
//   W = Wh + Wl (fp16 hi/lo, error ~2^-21). Total error ~2^-11/layer,
//   well under the 1e-3 gate. 33% less MMA work, 50% less A traffic
//   than the bf16 3-term scheme.
//   1) split_w:   W1/W2/WL -> fp16 hi/lo (WL padded 40->64 rows)
//   2) gemm_first: Y = fp16(X) @ W1^T   (in-register convert)
//   3) gather:    H = fp16(relu(mean(Y[nbrs])))
//   4) gemm_mid:  Y = H @ W2^T
//   5) gather
//   6) gemm_mid<64,40>: out = H @ WL^T
// ================================================================

#define FEAT 128
#define SAMPLE 25
#define CLASSES 40
#define MAXN 100000
#define RS 272   // smem row stride bytes: conflict-free ldmatrix

__device__ float  g_Y[(size_t)MAXN * FEAT];
__device__ __half g_H[(size_t)MAXN * FEAT];
__device__ __half g_W1hi[128 * 128], g_W1lo[128 * 128];
__device__ __half g_W2hi[128 * 128], g_W2lo[128 * 128];
__device__ __half g_WLhi[64 * 128],  g_WLlo[64 * 128];

__device__ __forceinline__ uint32_t smem_u32(const void* p) {
    uint32_t a;
    asm("{ .reg .u64 t; cvta.to.shared.u64 t, %1; cvt.u32.u64 %0, t; }" : "=r"(a) : "l"(p));
    return a;
}
__device__ __forceinline__ void ldsm4(uint32_t addr, uint32_t& r0, uint32_t& r1,
                                      uint32_t& r2, uint32_t& r3) {
    asm volatile("ldmatrix.sync.aligned.m8n8.x4.shared.b16 {%0,%1,%2,%3}, [%4];"
                 : "=r"(r0), "=r"(r1), "=r"(r2), "=r"(r3) : "r"(addr));
}
__device__ __forceinline__ void mma_f16(float* c, const uint32_t* a,
                                        uint32_t b0, uint32_t b1) {
    asm volatile(
        "mma.sync.aligned.m16n8k16.row.col.f32.f16.f16.f32 "
        "{%0,%1,%2,%3}, {%4,%5,%6,%7}, {%8,%9}, {%0,%1,%2,%3};"
        : "+f"(c[0]), "+f"(c[1]), "+f"(c[2]), "+f"(c[3])
        : "r"(a[0]), "r"(a[1]), "r"(a[2]), "r"(a[3]), "r"(b0), "r"(b1));
}

// ---------------- MMA core: 8 warps, CTA tile 128 x NOUT --------------------
// smem: [A 128*RS][Wh NOUT*RS][Wl NOUT*RS]
template<int NOUT, int CST>
__device__ __forceinline__ void mma_core_and_store(
    char* smem, float* __restrict__ C, int m0, int n)
{
    constexpr int OFF_WH = 128 * RS;
    constexpr int OFF_WL = OFF_WH + NOUT * RS;
    constexpr int WN = NOUT / 2;       // warp n-extent (64 or 32)
    constexpr int NT = WN / 8;         // n8 tiles per warp (8 or 4)

    const int tid  = threadIdx.x;
    const int wid  = tid >> 5;
    const int lane = tid & 31;
    const int wm   = wid >> 1;         // 0..3 -> m = wm*32
    const int wn   = wid & 1;          // 0..1 -> n = wn*WN

    const uint32_t sb = smem_u32(smem);
    const uint32_t aB  = sb;
    const uint32_t whB = sb + OFF_WH;
    const uint32_t wlB = sb + OFF_WL;

    const int l15   = lane & 15;
    const int aHalf = (lane & 16) ? 16 : 0;
    const uint32_t aRow0 = (uint32_t)((wm * 32 + l15) * RS + aHalf);
    const uint32_t aRow1 = aRow0 + 16 * RS;
    const int bRow  = (lane & 7) + ((lane & 16) ? 8 : 0);
    const int bHalf = (lane & 8) ? 16 : 0;
    uint32_t bRowByte[NT / 2];
    #pragma unroll
    for (int jp = 0; jp < NT / 2; jp++)
        bRowByte[jp] = (uint32_t)((wn * WN + jp * 16 + bRow) * RS + bHalf);

    float c[2][NT][4];
    #pragma unroll
    for (int mt = 0; mt < 2; mt++)
        #pragma unroll
        for (int j = 0; j < NT; j++)
            #pragma unroll
            for (int q = 0; q < 4; q++) c[mt][j][q] = 0.f;

    #pragma unroll
    for (int ks = 0; ks < 8; ks++) {
        const uint32_t kb = ks * 32;
        uint32_t a[2][4];
        ldsm4(aB + aRow0 + kb, a[0][0], a[0][1], a[0][2], a[0][3]);
        ldsm4(aB + aRow1 + kb, a[1][0], a[1][1], a[1][2], a[1][3]);
        uint32_t bh[NT][2], bl[NT][2];
        #pragma unroll
        for (int jp = 0; jp < NT / 2; jp++) {
            ldsm4(whB + bRowByte[jp] + kb,
                  bh[2 * jp][0], bh[2 * jp][1], bh[2 * jp + 1][0], bh[2 * jp + 1][1]);
            ldsm4(wlB + bRowByte[jp] + kb,
                  bl[2 * jp][0], bl[2 * jp][1], bl[2 * jp + 1][0], bl[2 * jp + 1][1]);
        }
        #pragma unroll
        for (int mt = 0; mt < 2; mt++)
            #pragma unroll
            for (int j = 0; j < NT; j++) {
                mma_f16(c[mt][j], a[mt], bh[j][0], bh[j][1]);
                mma_f16(c[mt][j], a[mt], bl[j][0], bl[j][1]);
            }
    }

    const int qrow = lane >> 2;
    const int qcol = (lane & 3) * 2;
    #pragma unroll
    for (int mt = 0; mt < 2; mt++) {
        #pragma unroll
        for (int half = 0; half < 2; half++) {
            int m_g = m0 + wm * 32 + mt * 16 + qrow + half * 8;
            if (m_g < n) {
                float* crow = C + (size_t)m_g * CST;
                #pragma unroll
                for (int j = 0; j < NT; j++) {
                    int n_g = wn * WN + j * 8 + qcol;
                    if (CST == 128 || n_g < CST) {
                        float2 v = make_float2(c[mt][j][half * 2], c[mt][j][half * 2 + 1]);
                        *reinterpret_cast<float2*>(crow + n_g) = v;
                    }
                }
            }
        }
    }
}

// W tile loader: NOUT rows x 128 fp16 (hi+lo), 256 threads
template<int NOUT>
__device__ __forceinline__ void load_w_tiles(
    char* smem, const __half* __restrict__ Wh, const __half* __restrict__ Wl)
{
    constexpr int OFF_WH = 128 * RS;
    constexpr int OFF_WL = OFF_WH + NOUT * RS;
    const int tid = threadIdx.x;
    #pragma unroll
    for (int i = 0; i < NOUT / 16; i++) {
        int t = i * 256 + tid;
        int row = t >> 4;
        int c16 = t & 15;
        size_t g = (size_t)row * 128 + c16 * 8;
        int off = row * RS + c16 * 16;
        *reinterpret_cast<uint4*>(smem + OFF_WH + off) =
            *reinterpret_cast<const uint4*>(Wh + g);
        *reinterpret_cast<uint4*>(smem + OFF_WL + off) =
            *reinterpret_cast<const uint4*>(Wl + g);
    }
}

// ---------------- kernel 2: Y = fp16(X) @ W1^T ------------------------------
__global__ __launch_bounds__(256, 2) void gemm_first_kernel(
    const float* __restrict__ X,
    const __half* __restrict__ Wh, const __half* __restrict__ Wl,
    float* __restrict__ C, int n)
{
    extern __shared__ char smem[];
    const int tid = threadIdx.x;
    const int m0  = blockIdx.x * 128;

    #pragma unroll
    for (int i = 0; i < 16; i++) {
        int t = i * 256 + tid;              // 4096 float4
        int row = t >> 5;
        int c4  = t & 31;
        int grow = m0 + row;
        float4 v = make_float4(0.f, 0.f, 0.f, 0.f);
        if (grow < n)
            v = __ldg(reinterpret_cast<const float4*>(X + (size_t)grow * 128) + c4);
        __half h[4] = { __float2half(v.x), __float2half(v.y),
                        __float2half(v.z), __float2half(v.w) };
        *reinterpret_cast<uint2*>(smem + row * RS + c4 * 8) =
            *reinterpret_cast<uint2*>(h);
    }
    load_w_tiles<128>(smem, Wh, Wl);
    __syncthreads();
    mma_core_and_store<128, 128>(smem, C, m0, n);
}

// ---------------- kernels 4/6: H(fp16) @ W^T --------------------------------
template<int NOUT, int CST>
__global__ __launch_bounds__(256, 2) void gemm_mid_kernel(
    const __half* __restrict__ A,
    const __half* __restrict__ Wh, const __half* __restrict__ Wl,
    float* __restrict__ C, int n)
{
    extern __shared__ char smem[];
    const int tid = threadIdx.x;
    const int m0  = blockIdx.x * 128;

    #pragma unroll
    for (int i = 0; i < 8; i++) {
        int t = i * 256 + tid;              // 2048 uint4
        int row = t >> 4;
        int c16 = t & 15;
        int grow = m0 + row;
        uint4 v = make_uint4(0, 0, 0, 0);
        if (grow < n)
            v = *reinterpret_cast<const uint4*>(A + (size_t)grow * 128 + c16 * 8);
        *reinterpret_cast<uint4*>(smem + row * RS + c16 * 16) = v;
    }
    load_w_tiles<NOUT>(smem, Wh, Wl);
    __syncthreads();
    mma_core_and_store<NOUT, CST>(smem, C, m0, n);
}

// ---------------- kernels 3/5: gather -> fp16 H ------------------------------
__global__ __launch_bounds__(256) void gather_h16_kernel(
    const float* __restrict__ Y, const int* __restrict__ nbrs,
    __half* __restrict__ H, int n)
{
    const int warp = (blockIdx.x * blockDim.x + threadIdx.x) >> 5;
    const int lane = threadIdx.x & 31;
    if (warp >= n) return;

    int idx = 0;
    if (lane < SAMPLE) idx = nbrs[(size_t)warp * SAMPLE + lane];

    float4 acc = make_float4(0.f, 0.f, 0.f, 0.f);
    #pragma unroll
    for (int j = 0; j < SAMPLE; j++) {
        int row = __shfl_sync(0xffffffffu, idx, j);
        float4 v = __ldg(reinterpret_cast<const float4*>(Y + (size_t)row * 128) + lane);
        acc.x += v.x; acc.y += v.y; acc.z += v.z; acc.w += v.w;
    }
    const float s = 1.0f / (float)SAMPLE;
    __half h[4] = { __float2half(fmaxf(acc.x * s, 0.f)),
                    __float2half(fmaxf(acc.y * s, 0.f)),
                    __float2half(fmaxf(acc.z * s, 0.f)),
                    __float2half(fmaxf(acc.w * s, 0.f)) };
    *(reinterpret_cast<uint2*>(H + (size_t)warp * 128) + lane) =
        *reinterpret_cast<uint2*>(h);
}

// ---------------- kernel 1: weight splitter (fp16 hi/lo) --------------------
__global__ void split_w_kernel(const float* __restrict__ W1,
                               const float* __restrict__ W2,
                               const float* __restrict__ WL,
                               __half* w1h, __half* w1l,
                               __half* w2h, __half* w2l,
                               __half* wlh, __half* wll)
{
    int i = blockIdx.x * blockDim.x + threadIdx.x;  // 0 .. 40959
    float v; __half *ph, *pl; int idx;
    if (i < 16384)      { v = W1[i];            ph = w1h; pl = w1l; idx = i; }
    else if (i < 32768) { idx = i - 16384; v = W2[idx]; ph = w2h; pl = w2l; }
    else if (i < 40960) {
        idx = i - 32768;                 // padded [64][128]
        int row = idx >> 7;
        v = (row < CLASSES) ? WL[idx] : 0.f;
        ph = wlh; pl = wll;
    } else return;
    __half h = __float2half(v);
    ph[idx] = h;
    pl[idx] = __float2half(v - __half2float(h));
}

// ================================================================
extern "C" void kernel_launch(void* const* d_in, const int* in_sizes, int n_in,
                              void* d_out, int out_size)
{
    const float* X    = (const float*)d_in[0];
    const int*   nbrs = (const int*)  d_in[1];
    const float* W1   = (const float*)d_in[2];
    const float* W2   = (const float*)d_in[3];
    const float* WL   = (const float*)d_in[4];
    float*       out  = (float*)d_out;
    const int n = in_sizes[1] / SAMPLE;

    float* Y;
    __half *H, *w1h, *w1l, *w2h, *w2l, *wlh, *wll;
    cudaGetSymbolAddress((void**)&Y,   g_Y);
    cudaGetSymbolAddress((void**)&H,   g_H);
    cudaGetSymbolAddress((void**)&w1h, g_W1hi);
    cudaGetSymbolAddress((void**)&w1l, g_W1lo);
    cudaGetSymbolAddress((void**)&w2h, g_W2hi);
    cudaGetSymbolAddress((void**)&w2l, g_W2lo);
    cudaGetSymbolAddress((void**)&wlh, g_WLhi);
    cudaGetSymbolAddress((void**)&wll, g_WLlo);

    const int SM128 = RS * (128 + 2 * 128);   // 104448
    const int SM64  = RS * (128 + 2 * 64);    //  69632
    cudaFuncSetAttribute(gemm_first_kernel,
                         cudaFuncAttributeMaxDynamicSharedMemorySize, SM128);
    cudaFuncSetAttribute(gemm_mid_kernel<128, 128>,
                         cudaFuncAttributeMaxDynamicSharedMemorySize, SM128);
    cudaFuncSetAttribute(gemm_mid_kernel<64, 40>,
                         cudaFuncAttributeMaxDynamicSharedMemorySize, SM64);

    const int gg = (n + 127) / 128;
    const int ag = (n + 7) / 8;

    split_w_kernel<<<160, 256>>>(W1, W2, WL, w1h, w1l, w2h, w2l, wlh, wll);
    gemm_first_kernel<<<gg, 256, SM128>>>(X, w1h, w1l, Y, n);
    gather_h16_kernel<<<ag, 256>>>(Y, nbrs, H, n);
    gemm_mid_kernel<128, 128><<<gg, 256, SM128>>>(H, w2h, w2l, Y, n);
    gather_h16_kernel<<<ag, 256>>>(Y, nbrs, H, n);
    gemm_mid_kernel<64, 40><<<gg, 256, SM64>>>(H, wlh, wll, out, n);
}

// round 10
// speedup vs baseline: 2.0200x; 1.3083x over previous
#include <cuda_runtime.h>
#include <cuda_fp16.h>
#include <cstdint>

// ================================================================
// AutoGNN, 6 launches — fp16 end-to-end intermediates:
//   W split hi/lo fp16 (error 2^-21); activations single fp16 plane.
//   Y carried in fp16 (halves gather L2 traffic; Y now L2-resident).
//   1) split_w:    W1/W2/WL -> fp16 hi/lo (WL padded 40->64 rows)
//   2) gemm_first: Y = fp16(X) @ W1^T          -> fp16 Y
//   3) gather:     H = fp16(relu(mean(Y[nbrs])))
//   4) gemm_mid:   Y = H @ W2^T                -> fp16 Y
//   5) gather
//   6) gemm_last:  out = H @ WL^T              -> fp32 out
// GEMM: mma.sync m16n8k16 fp16, 2-term W split, fp32 accum.
// ================================================================

#define FEAT 128
#define SAMPLE 25
#define CLASSES 40
#define MAXN 100000
#define RS 272   // smem row stride bytes: conflict-free ldmatrix

__device__ __half g_Y[(size_t)MAXN * FEAT];
__device__ __half g_H[(size_t)MAXN * FEAT];
__device__ __half g_W1hi[128 * 128], g_W1lo[128 * 128];
__device__ __half g_W2hi[128 * 128], g_W2lo[128 * 128];
__device__ __half g_WLhi[64 * 128],  g_WLlo[64 * 128];

__device__ __forceinline__ uint32_t smem_u32(const void* p) {
    uint32_t a;
    asm("{ .reg .u64 t; cvta.to.shared.u64 t, %1; cvt.u32.u64 %0, t; }" : "=r"(a) : "l"(p));
    return a;
}
__device__ __forceinline__ void ldsm4(uint32_t addr, uint32_t& r0, uint32_t& r1,
                                      uint32_t& r2, uint32_t& r3) {
    asm volatile("ldmatrix.sync.aligned.m8n8.x4.shared.b16 {%0,%1,%2,%3}, [%4];"
                 : "=r"(r0), "=r"(r1), "=r"(r2), "=r"(r3) : "r"(addr));
}
__device__ __forceinline__ void mma_f16(float* c, const uint32_t* a,
                                        uint32_t b0, uint32_t b1) {
    asm volatile(
        "mma.sync.aligned.m16n8k16.row.col.f32.f16.f16.f32 "
        "{%0,%1,%2,%3}, {%4,%5,%6,%7}, {%8,%9}, {%0,%1,%2,%3};"
        : "+f"(c[0]), "+f"(c[1]), "+f"(c[2]), "+f"(c[3])
        : "r"(a[0]), "r"(a[1]), "r"(a[2]), "r"(a[3]), "r"(b0), "r"(b1));
}

// ---------------- MMA core: 8 warps, CTA tile 128 x NOUT --------------------
// smem: [A 128*RS][Wh NOUT*RS][Wl NOUT*RS].  TOUT in {__half, float}.
template<int NOUT, int CST, typename TOUT>
__device__ __forceinline__ void mma_core_and_store(
    char* smem, TOUT* __restrict__ C, int m0, int n)
{
    constexpr int OFF_WH = 128 * RS;
    constexpr int OFF_WL = OFF_WH + NOUT * RS;
    constexpr int WN = NOUT / 2;       // warp n-extent (64 or 32)
    constexpr int NT = WN / 8;         // n8 tiles per warp (8 or 4)

    const int tid  = threadIdx.x;
    const int wid  = tid >> 5;
    const int lane = tid & 31;
    const int wm   = wid >> 1;         // 0..3 -> m = wm*32
    const int wn   = wid & 1;          // 0..1 -> n = wn*WN

    const uint32_t sb = smem_u32(smem);
    const uint32_t aB  = sb;
    const uint32_t whB = sb + OFF_WH;
    const uint32_t wlB = sb + OFF_WL;

    const int l15   = lane & 15;
    const int aHalf = (lane & 16) ? 16 : 0;
    const uint32_t aRow0 = (uint32_t)((wm * 32 + l15) * RS + aHalf);
    const uint32_t aRow1 = aRow0 + 16 * RS;
    const int bRow  = (lane & 7) + ((lane & 16) ? 8 : 0);
    const int bHalf = (lane & 8) ? 16 : 0;
    uint32_t bRowByte[NT / 2];
    #pragma unroll
    for (int jp = 0; jp < NT / 2; jp++)
        bRowByte[jp] = (uint32_t)((wn * WN + jp * 16 + bRow) * RS + bHalf);

    float c[2][NT][4];
    #pragma unroll
    for (int mt = 0; mt < 2; mt++)
        #pragma unroll
        for (int j = 0; j < NT; j++)
            #pragma unroll
            for (int q = 0; q < 4; q++) c[mt][j][q] = 0.f;

    #pragma unroll
    for (int ks = 0; ks < 8; ks++) {
        const uint32_t kb = ks * 32;
        uint32_t a[2][4];
        ldsm4(aB + aRow0 + kb, a[0][0], a[0][1], a[0][2], a[0][3]);
        ldsm4(aB + aRow1 + kb, a[1][0], a[1][1], a[1][2], a[1][3]);
        uint32_t bh[NT][2], bl[NT][2];
        #pragma unroll
        for (int jp = 0; jp < NT / 2; jp++) {
            ldsm4(whB + bRowByte[jp] + kb,
                  bh[2 * jp][0], bh[2 * jp][1], bh[2 * jp + 1][0], bh[2 * jp + 1][1]);
            ldsm4(wlB + bRowByte[jp] + kb,
                  bl[2 * jp][0], bl[2 * jp][1], bl[2 * jp + 1][0], bl[2 * jp + 1][1]);
        }
        #pragma unroll
        for (int mt = 0; mt < 2; mt++)
            #pragma unroll
            for (int j = 0; j < NT; j++) {
                mma_f16(c[mt][j], a[mt], bh[j][0], bh[j][1]);
                mma_f16(c[mt][j], a[mt], bl[j][0], bl[j][1]);
            }
    }

    const int qrow = lane >> 2;
    const int qcol = (lane & 3) * 2;
    #pragma unroll
    for (int mt = 0; mt < 2; mt++) {
        #pragma unroll
        for (int half = 0; half < 2; half++) {
            int m_g = m0 + wm * 32 + mt * 16 + qrow + half * 8;
            if (m_g < n) {
                TOUT* crow = C + (size_t)m_g * CST;
                #pragma unroll
                for (int j = 0; j < NT; j++) {
                    int n_g = wn * WN + j * 8 + qcol;
                    if (CST == 128 || n_g < CST) {
                        float v0 = c[mt][j][half * 2];
                        float v1 = c[mt][j][half * 2 + 1];
                        if constexpr (sizeof(TOUT) == 2) {
                            __half2 hv = __floats2half2_rn(v0, v1);
                            *reinterpret_cast<__half2*>(crow + n_g) = hv;
                        } else {
                            *reinterpret_cast<float2*>(crow + n_g) =
                                make_float2(v0, v1);
                        }
                    }
                }
            }
        }
    }
}

// W tile loader: NOUT rows x 128 fp16 (hi+lo), 256 threads
template<int NOUT>
__device__ __forceinline__ void load_w_tiles(
    char* smem, const __half* __restrict__ Wh, const __half* __restrict__ Wl)
{
    constexpr int OFF_WH = 128 * RS;
    constexpr int OFF_WL = OFF_WH + NOUT * RS;
    const int tid = threadIdx.x;
    #pragma unroll
    for (int i = 0; i < NOUT / 16; i++) {
        int t = i * 256 + tid;
        int row = t >> 4;
        int c16 = t & 15;
        size_t g = (size_t)row * 128 + c16 * 8;
        int off = row * RS + c16 * 16;
        *reinterpret_cast<uint4*>(smem + OFF_WH + off) =
            *reinterpret_cast<const uint4*>(Wh + g);
        *reinterpret_cast<uint4*>(smem + OFF_WL + off) =
            *reinterpret_cast<const uint4*>(Wl + g);
    }
}

// ---------------- kernel 2: Y(fp16) = fp16(X) @ W1^T ------------------------
__global__ __launch_bounds__(256, 2) void gemm_first_kernel(
    const float* __restrict__ X,
    const __half* __restrict__ Wh, const __half* __restrict__ Wl,
    __half* __restrict__ C, int n)
{
    extern __shared__ char smem[];
    const int tid = threadIdx.x;
    const int m0  = blockIdx.x * 128;

    #pragma unroll
    for (int i = 0; i < 16; i++) {
        int t = i * 256 + tid;              // 4096 float4
        int row = t >> 5;
        int c4  = t & 31;
        int grow = m0 + row;
        float4 v = make_float4(0.f, 0.f, 0.f, 0.f);
        if (grow < n)
            v = __ldg(reinterpret_cast<const float4*>(X + (size_t)grow * 128) + c4);
        __half h[4] = { __float2half(v.x), __float2half(v.y),
                        __float2half(v.z), __float2half(v.w) };
        *reinterpret_cast<uint2*>(smem + row * RS + c4 * 8) =
            *reinterpret_cast<uint2*>(h);
    }
    load_w_tiles<128>(smem, Wh, Wl);
    __syncthreads();
    mma_core_and_store<128, 128>(smem, C, m0, n);
}

// ---------------- kernels 4/6: H(fp16) @ W^T --------------------------------
template<int NOUT, int CST, typename TOUT>
__global__ __launch_bounds__(256, 2) void gemm_mid_kernel(
    const __half* __restrict__ A,
    const __half* __restrict__ Wh, const __half* __restrict__ Wl,
    TOUT* __restrict__ C, int n)
{
    extern __shared__ char smem[];
    const int tid = threadIdx.x;
    const int m0  = blockIdx.x * 128;

    #pragma unroll
    for (int i = 0; i < 8; i++) {
        int t = i * 256 + tid;              // 2048 uint4
        int row = t >> 4;
        int c16 = t & 15;
        int grow = m0 + row;
        uint4 v = make_uint4(0, 0, 0, 0);
        if (grow < n)
            v = *reinterpret_cast<const uint4*>(A + (size_t)grow * 128 + c16 * 8);
        *reinterpret_cast<uint4*>(smem + row * RS + c16 * 16) = v;
    }
    load_w_tiles<NOUT>(smem, Wh, Wl);
    __syncthreads();
    mma_core_and_store<NOUT, CST>(smem, C, m0, n);
}

// ---------------- kernels 3/5: gather fp16 Y -> fp16 H ----------------------
__global__ __launch_bounds__(256) void gather_h16_kernel(
    const __half* __restrict__ Y, const int* __restrict__ nbrs,
    __half* __restrict__ H, int n)
{
    const int warp = (blockIdx.x * blockDim.x + threadIdx.x) >> 5;
    const int lane = threadIdx.x & 31;
    if (warp >= n) return;

    int idx = 0;
    if (lane < SAMPLE) idx = nbrs[(size_t)warp * SAMPLE + lane];

    float acc[4] = { 0.f, 0.f, 0.f, 0.f };
    #pragma unroll
    for (int j = 0; j < SAMPLE; j++) {
        int row = __shfl_sync(0xffffffffu, idx, j);
        uint2 u = __ldg(reinterpret_cast<const uint2*>(Y + (size_t)row * 128) + lane);
        __half2 p0 = *reinterpret_cast<__half2*>(&u.x);
        __half2 p1 = *reinterpret_cast<__half2*>(&u.y);
        float2 f0 = __half22float2(p0);
        float2 f1 = __half22float2(p1);
        acc[0] += f0.x; acc[1] += f0.y; acc[2] += f1.x; acc[3] += f1.y;
    }
    const float s = 1.0f / (float)SAMPLE;
    __half h[4] = { __float2half(fmaxf(acc[0] * s, 0.f)),
                    __float2half(fmaxf(acc[1] * s, 0.f)),
                    __float2half(fmaxf(acc[2] * s, 0.f)),
                    __float2half(fmaxf(acc[3] * s, 0.f)) };
    *(reinterpret_cast<uint2*>(H + (size_t)warp * 128) + lane) =
        *reinterpret_cast<uint2*>(h);
}

// ---------------- kernel 1: weight splitter (fp16 hi/lo) --------------------
__global__ void split_w_kernel(const float* __restrict__ W1,
                               const float* __restrict__ W2,
                               const float* __restrict__ WL,
                               __half* w1h, __half* w1l,
                               __half* w2h, __half* w2l,
                               __half* wlh, __half* wll)
{
    int i = blockIdx.x * blockDim.x + threadIdx.x;  // 0 .. 40959
    float v; __half *ph, *pl; int idx;
    if (i < 16384)      { v = W1[i];            ph = w1h; pl = w1l; idx = i; }
    else if (i < 32768) { idx = i - 16384; v = W2[idx]; ph = w2h; pl = w2l; }
    else if (i < 40960) {
        idx = i - 32768;                 // padded [64][128]
        int row = idx >> 7;
        v = (row < CLASSES) ? WL[idx] : 0.f;
        ph = wlh; pl = wll;
    } else return;
    __half h = __float2half(v);
    ph[idx] = h;
    pl[idx] = __float2half(v - __half2float(h));
}

// ================================================================
extern "C" void kernel_launch(void* const* d_in, const int* in_sizes, int n_in,
                              void* d_out, int out_size)
{
    const float* X    = (const float*)d_in[0];
    const int*   nbrs = (const int*)  d_in[1];
    const float* W1   = (const float*)d_in[2];
    const float* W2   = (const float*)d_in[3];
    const float* WL   = (const float*)d_in[4];
    float*       out  = (float*)d_out;
    const int n = in_sizes[1] / SAMPLE;

    __half *Y, *H, *w1h, *w1l, *w2h, *w2l, *wlh, *wll;
    cudaGetSymbolAddress((void**)&Y,   g_Y);
    cudaGetSymbolAddress((void**)&H,   g_H);
    cudaGetSymbolAddress((void**)&w1h, g_W1hi);
    cudaGetSymbolAddress((void**)&w1l, g_W1lo);
    cudaGetSymbolAddress((void**)&w2h, g_W2hi);
    cudaGetSymbolAddress((void**)&w2l, g_W2lo);
    cudaGetSymbolAddress((void**)&wlh, g_WLhi);
    cudaGetSymbolAddress((void**)&wll, g_WLlo);

    const int SM128 = RS * (128 + 2 * 128);   // 104448
    const int SM64  = RS * (128 + 2 * 64);    //  69632
    cudaFuncSetAttribute(gemm_first_kernel,
                         cudaFuncAttributeMaxDynamicSharedMemorySize, SM128);
    cudaFuncSetAttribute(gemm_mid_kernel<128, 128, __half>,
                         cudaFuncAttributeMaxDynamicSharedMemorySize, SM128);
    cudaFuncSetAttribute(gemm_mid_kernel<64, 40, float>,
                         cudaFuncAttributeMaxDynamicSharedMemorySize, SM64);

    const int gg = (n + 127) / 128;
    const int ag = (n + 7) / 8;

    split_w_kernel<<<160, 256>>>(W1, W2, WL, w1h, w1l, w2h, w2l, wlh, wll);
    gemm_first_kernel<<<gg, 256, SM128>>>(X, w1h, w1l, Y, n);
    gather_h16_kernel<<<ag, 256>>>(Y, nbrs, H, n);
    gemm_mid_kernel<128, 128, __half><<<gg, 256, SM128>>>(H, w2h, w2l, Y, n);
    gather_h16_kernel<<<ag, 256>>>(Y, nbrs, H, n);
    gemm_mid_kernel<64, 40, float><<<gg, 256, SM64>>>(H, wlh, wll, out, n);
}